// round 11
// baseline (speedup 1.0000x reference)
#include <cuda_runtime.h>

// LengthRegulator: B=32, T=1024, C=384, M=4096. Durations int32; totals appended
// to out as float32 values (confirmed R4/R5).
//
// R11 = R10 engine + (1) PDL overlap of prep with gather prologue,
//       (2) hoisted row/c math (QTR is an exact multiple of C4).

#define BB 32
#define TT 1024
#define CC 384
#define MM 4096
#define C4 (CC / 4)                              // 96 float4 per row
#define MAIN_ELEMS ((long long)BB * MM * CC)     // 50,331,648
#define N4 (BB * MM * C4)                        // 12,582,912 float4
#define QTR (N4 / 4)                             // 3,145,728  (= 32768 rows * C4)
#define RQTR (QTR / C4)                          // 32768 rows per stream
#define SEG 8                                    // prep blocks per batch
#define FSEG (MM / SEG)                          // 512 frames per prep block

__device__ int g_tok[BB * MM];     // token index per frame, -1 => zero-fill

// ---------------------------------------------------------------------------
// Prep: grid (SEG, BB) = 256 CTAs, 512 threads. Each block scans its batch's
// 1024 durations (int2 pairs, shfl scan) and resolves FSEG frames (1/thread).
// ---------------------------------------------------------------------------
__global__ __launch_bounds__(512) void lr_prep_kernel(
        const int2* __restrict__ dur2,
        float* __restrict__ out_base) {
    __shared__ int cs[TT];
    __shared__ int wsum[16];

    const int b   = blockIdx.y;
    const int tid = threadIdx.x;                 // 0..511
    const int lane = tid & 31;
    const int w    = tid >> 5;                   // warp 0..15

    const int2 d = dur2[b * (TT / 2) + tid];
    const int e1 = d.y;
    int pair = d.x + d.y;
    #pragma unroll
    for (int off = 1; off < 32; off <<= 1) {
        int n = __shfl_up_sync(0xffffffffu, pair, off);
        if (lane >= off) pair += n;
    }
    if (lane == 31) wsum[w] = pair;
    __syncthreads();
    if (tid < 32) {
        int s = (tid < 16) ? wsum[tid] : 0;
        #pragma unroll
        for (int off = 1; off < 32; off <<= 1) {
            int n = __shfl_up_sync(0xffffffffu, s, off);
            if (lane >= off) s += n;
        }
        if (tid < 16) wsum[tid] = s;
    }
    __syncthreads();
    const int base = (w > 0) ? wsum[w - 1] : 0;
    cs[2 * tid + 1] = base + pair;               // inclusive cumsum
    cs[2 * tid]     = base + pair - e1;
    __syncthreads();

    const int total = cs[TT - 1];
    if (blockIdx.x == 0 && tid == 0)
        out_base[MAIN_ELEMS + b] = (float)total; // total as float32 value

    const int f = blockIdx.x * FSEG + tid;       // one frame per thread
    int pos = 0;                                  // upper_bound, bit construction
    #pragma unroll
    for (int step = TT / 2; step > 0; step >>= 1) {
        int cand = pos + step;                   // cand-1 <= 1022
        if (cs[cand - 1] <= f) pos = cand;
    }
    g_tok[b * MM + f] = (f < total) ? pos : -1;
}

// ---------------------------------------------------------------------------
// Gather: 4 independent coalesced float4 streams per thread (MLP=4).
// Streams are row-aligned slices (QTR % C4 == 0), so c is shared and rows are
// row0 + k*RQTR. PDL: index math runs before the dependency sync.
// ---------------------------------------------------------------------------
__global__ void lr_gather_kernel(const float4* __restrict__ x4,
                                 float4* __restrict__ out4) {
    const int i = blockIdx.x * blockDim.x + threadIdx.x;     // < QTR
    const int row0 = i / C4;                     // < RQTR
    const int c    = i - row0 * C4;

    int row[4], b[4];
    #pragma unroll
    for (int k = 0; k < 4; ++k) {
        row[k] = row0 + k * RQTR;                // b*MM + f
        b[k]   = row[k] >> 12;                   // row / MM
    }

    cudaGridDependencySynchronize();             // wait for prep (PDL)

    int tok[4];
    #pragma unroll
    for (int k = 0; k < 4; ++k) tok[k] = g_tok[row[k]];

    float4 val[4];
    #pragma unroll
    for (int k = 0; k < 4; ++k) {
        val[k] = make_float4(0.f, 0.f, 0.f, 0.f);
        if (tok[k] >= 0)
            val[k] = __ldg(&x4[(b[k] * TT + tok[k]) * C4 + c]);
    }

    #pragma unroll
    for (int k = 0; k < 4; ++k)
        __stcs(&out4[i + k * QTR], val[k]);
}

// ---------------------------------------------------------------------------

extern "C" void kernel_launch(void* const* d_in, const int* in_sizes, int n_in,
                              void* d_out, int out_size) {
    const float4* x4 = (const float4*)d_in[0];
    const int2* dur2 = (const int2*)d_in[1];
    float* out = (float*)d_out;

    dim3 gprep(SEG, BB);                         // (8, 32) = 256 CTAs
    lr_prep_kernel<<<gprep, 512>>>(dur2, out);

    // Gather launched with programmatic dependent launch: its prologue overlaps
    // prep; correctness guarded by cudaGridDependencySynchronize() in-kernel.
    cudaLaunchConfig_t cfg = {};
    cfg.gridDim  = dim3(QTR / 256, 1, 1);
    cfg.blockDim = dim3(256, 1, 1);
    cudaLaunchAttribute attr[1];
    attr[0].id = cudaLaunchAttributeProgrammaticStreamSerialization;
    attr[0].val.programmaticStreamSerializationAllowed = 1;
    cfg.attrs = attr;
    cfg.numAttrs = 1;
    cudaLaunchKernelEx(&cfg, lr_gather_kernel, x4, (float4*)d_out);
}

// round 12
// speedup vs baseline: 1.0118x; 1.0118x over previous
#include <cuda_runtime.h>

// LengthRegulator: B=32, T=1024, C=384, M=4096. Durations int32; totals appended
// to out as float32 values (confirmed R4/R5).
//
// R12: prep (R10, proven) + frame-blocked gather: each 256-thread block owns
// 8 consecutive frames, toks staged in smem -> x rows read once per block
// (L1 reuse), cutting the DRAM/L2 read stream that rides along the 201MB write.

#define BB 32
#define TT 1024
#define CC 384
#define MM 4096
#define C4 (CC / 4)                              // 96 float4 per row
#define MAIN_ELEMS ((long long)BB * MM * CC)     // 50,331,648
#define SEG 8                                    // prep blocks per batch
#define FSEG (MM / SEG)                          // 512 frames per prep block
#define FPB 8                                    // frames per gather block
#define GT 256                                   // gather threads per block
#define EPB (FPB * C4)                           // 768 float4 per gather block

__device__ int g_tok[BB * MM];     // token index per frame, -1 => zero-fill

// ---------------------------------------------------------------------------
// Prep: grid (SEG, BB) = 256 CTAs, 512 threads. Each block scans its batch's
// 1024 durations (int2 pairs, shfl scan) and resolves FSEG frames (1/thread).
// ---------------------------------------------------------------------------
__global__ __launch_bounds__(512) void lr_prep_kernel(
        const int2* __restrict__ dur2,
        float* __restrict__ out_base) {
    __shared__ int cs[TT];
    __shared__ int wsum[16];

    const int b   = blockIdx.y;
    const int tid = threadIdx.x;                 // 0..511
    const int lane = tid & 31;
    const int w    = tid >> 5;                   // warp 0..15

    const int2 d = dur2[b * (TT / 2) + tid];
    const int e1 = d.y;
    int pair = d.x + d.y;
    #pragma unroll
    for (int off = 1; off < 32; off <<= 1) {
        int n = __shfl_up_sync(0xffffffffu, pair, off);
        if (lane >= off) pair += n;
    }
    if (lane == 31) wsum[w] = pair;
    __syncthreads();
    if (tid < 32) {
        int s = (tid < 16) ? wsum[tid] : 0;
        #pragma unroll
        for (int off = 1; off < 32; off <<= 1) {
            int n = __shfl_up_sync(0xffffffffu, s, off);
            if (lane >= off) s += n;
        }
        if (tid < 16) wsum[tid] = s;
    }
    __syncthreads();
    const int base = (w > 0) ? wsum[w - 1] : 0;
    cs[2 * tid + 1] = base + pair;               // inclusive cumsum
    cs[2 * tid]     = base + pair - e1;
    __syncthreads();

    const int total = cs[TT - 1];
    if (blockIdx.x == 0 && tid == 0)
        out_base[MAIN_ELEMS + b] = (float)total; // total as float32 value

    const int f = blockIdx.x * FSEG + tid;       // one frame per thread
    int pos = 0;                                  // upper_bound, bit construction
    #pragma unroll
    for (int step = TT / 2; step > 0; step >>= 1) {
        int cand = pos + step;                   // cand-1 <= 1022
        if (cs[cand - 1] <= f) pos = cand;
    }
    g_tok[b * MM + f] = (f < total) ? pos : -1;
}

// ---------------------------------------------------------------------------
// Frame-blocked gather: grid (MM/FPB, BB) = (512, 32), 256 threads.
// 8 frames/block; toks in smem; every thread streams 3 independent float4.
// All threads of the block read the same 2-3 x rows -> L1 hits after first
// touch; __stcs stores keep x resident in L2 across blocks.
// ---------------------------------------------------------------------------
__global__ __launch_bounds__(GT) void lr_gather_kernel(
        const float4* __restrict__ x4,
        float4* __restrict__ out4) {
    __shared__ int stok[FPB];
    const int b  = blockIdx.y;
    const int f0 = blockIdx.x * FPB;
    const int tid = threadIdx.x;

    if (tid < FPB)
        stok[tid] = g_tok[b * MM + f0 + tid];
    __syncthreads();

    const int obase = (b * MM + f0) * C4;        // < 12.6M, fits int
    const int xbase = b * TT * C4;

    float4 val[3];
    int eo[3];
    #pragma unroll
    for (int k = 0; k < 3; ++k) {
        const int e  = k * GT + tid;             // 0..767
        const int fl = e / C4;                   // local frame 0..7
        const int c  = e - fl * C4;
        const int tok = stok[fl];
        eo[k] = e;
        val[k] = make_float4(0.f, 0.f, 0.f, 0.f);
        if (tok >= 0)
            val[k] = __ldg(&x4[xbase + tok * C4 + c]);
    }
    #pragma unroll
    for (int k = 0; k < 3; ++k)
        __stcs(&out4[obase + eo[k]], val[k]);
}

// ---------------------------------------------------------------------------

extern "C" void kernel_launch(void* const* d_in, const int* in_sizes, int n_in,
                              void* d_out, int out_size) {
    const float4* x4 = (const float4*)d_in[0];
    const int2* dur2 = (const int2*)d_in[1];
    float* out = (float*)d_out;

    dim3 gprep(SEG, BB);                         // (8, 32) = 256 CTAs
    lr_prep_kernel<<<gprep, 512>>>(dur2, out);

    dim3 gg(MM / FPB, BB);                       // (512, 32) = 16384 CTAs
    lr_gather_kernel<<<gg, GT>>>(x4, (float4*)d_out);
}